// round 14
// baseline (speedup 1.0000x reference)
#include <cuda_runtime.h>
#include <math.h>

#define NMODES 6400
#define MMAX 80
#define GROUPS 25          // NMODES / 256 (s1 grid)
#define GSZ 256
#define SCHUNK 64          // samples per chunk
#define SH 32              // SCHUNK/2 packed f32x2 accumulators
#define NCB 1024           // bucket table size (chunks); N=44100 -> 690 chunks
#define PBLK 296           // persistent plate blocks = 2/SM * 148 (co-resident)

typedef unsigned long long u64;

// ---------------- static device scratch (no runtime allocation) -------------
__device__ float4 gA0[NMODES], gB0[NMODES];   // staging (mode-index order)
__device__ float4 gA[NMODES],  gB[NMODES];    // sorted by lifetime desc
__device__ int    gLc[NMODES];                // live-chunk count per mode
__device__ int    gRank[NMODES];              // deterministic rank in (group,bucket)
__device__ int    gH[GROUPS][NCB];            // per-group bucket histograms
__device__ int    gGOff[GROUPS][NCB];         // cross-group prefix per bucket
__device__ int    gBase[NCB];                 // live count L(c) (sorted prefix bound)
__device__ unsigned int gPeakBits;
__device__ int gSyncA;  __device__ volatile int gFlagA;   // barrier 1
__device__ int gSyncB;  __device__ volatile int gFlagB;   // barrier 2

// ---------------- f32x2 packed helpers (Blackwell FFMA2 path) ---------------
__device__ __forceinline__ u64 pack2(float lo, float hi) {
    u64 r; asm("mov.b64 %0, {%1, %2};" : "=l"(r) : "f"(lo), "f"(hi)); return r;
}
__device__ __forceinline__ u64 fma2(u64 a, u64 b, u64 c) {
    u64 d; asm("fma.rn.f32x2 %0, %1, %2, %3;" : "=l"(d) : "l"(a), "l"(b), "l"(c)); return d;
}
__device__ __forceinline__ u64 mul2(u64 a, u64 b) {
    u64 d; asm("mul.rn.f32x2 %0, %1, %2;" : "=l"(d) : "l"(a), "l"(b)); return d;
}
__device__ __forceinline__ u64 add2(u64 a, u64 b) {
    u64 d; asm("add.rn.f32x2 %0, %1, %2;" : "=l"(d) : "l"(a), "l"(b)); return d;
}

__device__ __forceinline__ float softplusf(float x) {
    return (x > 20.0f) ? x : log1pf(expf(x));
}

// ---------------------------------------------------------------------------
// S1: per-mode precompute (fp32) + per-group histogram + deterministic rank.
// grid = 25 x 256.  Also resets barrier/peak state for this replay.
// ---------------------------------------------------------------------------
__global__ void __launch_bounds__(GSZ) s1_kernel(
    const float* __restrict__ pmu, const float* __restrict__ pD,
    const float* __restrict__ pT0, const float* __restrict__ pLy,
    const float* __restrict__ pxo, const float* __restrict__ pyo, int NC)
{
    const int g = blockIdx.x, t = threadIdx.x;
    const int i = g * GSZ + t;
    const int warp = t >> 5, lane = t & 31;

    if (i == 0) { gPeakBits = 0u; gSyncA = 0; gFlagA = 0; gSyncB = 0; gFlagB = 0; }

    float mu   = softplusf(pmu[0]) + 1e-4f;
    float Dmu  = softplusf(pD[0])  + 1e-4f;
    float T0mu = softplusf(pT0[0]) + 1e-4f;
    float Ly = 1.1f + (4.0f - 1.1f) * ((tanhf(pLy[0]) + 1.0f) * 0.5f);
    const float LX = 0.5f;
    float xo = 0.49f * LX + (1.0f - 0.49f) * LX * ((tanhf(pxo[0]) + 1.0f) * 0.5f);
    float yo = 0.51f * Ly + (1.0f - 0.51f) * Ly * ((tanhf(pyo[0]) + 1.0f) * 0.5f);

    const float PI  = 3.14159265358979323846f;
    const float Kf  = (float)(1.0 / 44100.0);
    const float MAXOM = (float)(10000.0 * 2.0 * 3.141592653589793);
    const float MINOM = (float)(20.0 * 2.0 * 3.141592653589793);
    const double OM2   = 2.0 * 3.141592653589793 * 500.0;
    const double DOMSQ = OM2 * OM2;
    const double LN10T3 = 3.0 * 2.302585092994045684;
    const float ALPHA = (float)(LN10T3 / DOMSQ * (DOMSQ / 6.0));
    const float BETA  = (float)(LN10T3 / DOMSQ * (1.0 / 1.0 - 1.0 / 6.0));

    float m  = (float)(i / MMAX + 1);
    float nn = (float)(i % MMAX + 1);

    // omega / validity path identical (fp32) to the known-passing kernel
    float t1 = (m * PI) / LX;
    float t2 = (nn * PI) / Ly;
    float g1 = t1 * t1 + t2 * t2;
    float w2 = T0mu * g1 + (Dmu * g1) * g1;
    w2 = fmaxf(w2, 0.0f);
    float omega = sqrtf(w2);
    int valid = (omega <= MAXOM) && (omega >= MINOM);

    float sigma = ALPHA + BETA * (omega * omega);
    float xi = 0.1f * LX, yi = 0.1f * Ly;
    float in_w  = cosf(((xi * PI) * m) / LX) * cosf(((yi * PI) * nn) / Ly);
    float out_w = cosf(((xo * PI) * m) / LX) * cosf(((yo * PI) * nn) / Ly);
    float ms = 0.25f * mu * LX * Ly;
    float P  = out_w * in_w * (Kf * Kf) * expf(-sigma * Kf) / ms;

    float thK  = omega * Kf;
    float sigK = sigma * Kf;

    float sth, cth;
    sincosf(thK, &sth, &cth);
    float r   = expf(-sigK);
    float r2  = r * r;
    float c2  = fmaf(-2.0f * sth, sth, 1.0f);   // cos(2*thK) = 1 - 2 sin^2
    float a2  = 2.0f * r2 * c2;
    float nb2 = -(r2 * r2);
    float C   = P / (sth + 1e-8f);

    float cutoff = 20.0f / sigK;                // live while sigK*(n-1) <= 20
    int lc = 0;
    if (valid) {
        lc = (int)floorf((cutoff + 1.0f) / 64.0f) + 1;
        lc = max(0, min(lc, min(NC, NCB - 1)));
    }

    gA0[i] = make_float4(a2, nb2, C, r);        // .w = e^{-sigK} (plate seed)
    gB0[i] = make_float4(thK, sth, cth, sigK);
    gLc[i] = lc;

    // deterministic rank within (group,bucket): match-any within warp,
    // fixed warp order across warps
    __shared__ int sh_h[NCB];
    for (int b = t; b < NCB; b += GSZ) sh_h[b] = 0;
    __syncthreads();

    unsigned msk = __match_any_sync(0xFFFFFFFFu, lc);
    int riw    = __popc(msk & ((1u << lane) - 1u));
    int leader = __ffs(msk) - 1;
    int cnt    = __popc(msk);
    int rk = 0;
    #pragma unroll
    for (int w = 0; w < 8; ++w) {
        if (warp == w) {
            int base = 0;
            if (lane == leader) base = atomicAdd(&sh_h[lc], cnt);
            base = __shfl_sync(0xFFFFFFFFu, base, leader);
            rk = base + riw;
        }
        __syncthreads();
    }
    gRank[i] = rk;
    for (int b = t; b < NCB; b += GSZ) gH[g][b] = sh_h[b];
}

// ---------------------------------------------------------------------------
// S2: one block x 1024. Group-prefix table (byproduct of running sum) +
// bucket totals -> suffix scan -> gBase (=L(b)).
// ---------------------------------------------------------------------------
__global__ void __launch_bounds__(1024) s2_kernel(int NC)
{
    __shared__ int incl[NCB];
    __shared__ int orig[NCB];
    const int t = threadIdx.x;
    const int NB = min(NC, NCB - 1);            // max bucket index
    const int b = NB - t;                       // reversed mapping

    int s = 0;
    if (b >= 0) {
        #pragma unroll
        for (int g = 0; g < GROUPS; ++g) {
            gGOff[g][b] = s;                    // prefix over earlier groups
            s += gH[g][b];
        }
    }
    incl[t] = s; orig[t] = s;
    __syncthreads();

    for (int off = 1; off <= NB; off <<= 1) {
        int v = (t >= off && t <= NB) ? incl[t - off] : 0;
        __syncthreads();
        if (t <= NB) incl[t] += v;
        __syncthreads();
    }
    if (b >= 0) gBase[b] = incl[t] - orig[t];   // strict suffix sum = L(b)
}

// ---------------------------------------------------------------------------
// Persistent plate: scatter -> grid barrier -> sorted compute (balanced
// boustrophedon chunk schedule) -> grid barrier -> normalize.
// ---------------------------------------------------------------------------
struct Chain { u64 vc, vp, A2, nB2; };

__device__ __forceinline__ Chain seed_chain(float4 A, float4 B,
                                            float n0f, float n0m1, bool on)
{
    float s0, c0;
    sincosf(n0f * B.x, &s0, &c0);               // accurate phase re-seed
    float E0   = __expf(-B.w * n0m1);
    float r    = A.w;                           // e^{-sigK} precomputed
    float rinv = __frcp_rn(r);

    float sp1 = fmaf(s0, B.z,  c0 * B.y);       // sin((n0+1)θ)
    float sm1 = fmaf(s0, B.z, -c0 * B.y);       // sin((n0-1)θ)
    float sm2 = fmaf(2.0f * B.z, sm1, -s0);     // sin((n0-2)θ)

    float CE = on ? (A.z * E0) : 0.0f;
    Chain ch;
    ch.vc  = pack2(CE * s0, CE * r * sp1);                     // y(n0), y(n0+1)
    ch.vp  = pack2(CE * (rinv * rinv) * sm2, CE * rinv * sm1); // y(n0-2), y(n0-1)
    ch.A2  = pack2(A.x, A.x);
    ch.nB2 = pack2(A.y, A.y);
    return ch;
}

__device__ __forceinline__ void grid_barrier(int* syncp, volatile int* flagp)
{
    __threadfence();
    __syncthreads();
    if (threadIdx.x == 0) {
        int arrived = atomicAdd(syncp, 1);
        if (arrived == (int)gridDim.x - 1) {
            __threadfence();
            *flagp = 1;
        }
        while (*flagp == 0) {}
    }
    __syncthreads();
    __threadfence();
}

__global__ void __launch_bounds__(256, 2) plate_kernel(float* __restrict__ out, int N, int NC)
{
    const int lane = threadIdx.x & 31;
    const int warp = threadIdx.x >> 5;
    __shared__ u64 sred[8][33];

    // ---- Phase A: scatter modes into lifetime-descending order -------------
    {
        int i = blockIdx.x * 256 + threadIdx.x;
        if (i < NMODES) {
            int g = i >> 8;
            int lc = gLc[i];
            int pos = gBase[lc] + gGOff[g][lc] + gRank[i];
            gA[pos] = gA0[i];
            gB[pos] = gB0[i];
        }
    }
    grid_barrier(&gSyncA, &gFlagA);

    // ---- Phase B: sorted compute, boustrophedon static schedule ------------
    for (int k = 0; k * PBLK < NC; ++k) {
        int base = k * PBLK;
        int c = (k & 1) ? (base + PBLK - 1 - (int)blockIdx.x)
                        : (base + (int)blockIdx.x);
        if (c >= NC) continue;

        const int n0 = c * SCHUNK;
        const float n0f  = (float)n0;
        const float n0m1 = n0f - 1.0f;
        const int Lc = gBase[c];                // live modes = sorted prefix

        u64 acc[SH];
        #pragma unroll
        for (int j = 0; j < SH; ++j) acc[j] = 0ull;

        #pragma unroll 1
        for (int i = threadIdx.x; i < Lc; i += 512) {
            int ib = i + 256;
            bool on2 = ib < Lc;
            int i2 = on2 ? ib : i;              // duplicate w/ CE=0 past end

            float4 A1 = gA[i],  B1 = gB[i];
            float4 A2_ = gA[i2], B2 = gB[i2];
            Chain ca = seed_chain(A1, B1, n0f, n0m1, true);
            Chain cb = seed_chain(A2_, B2, n0f, n0m1, on2);

            acc[0] = add2(acc[0], add2(ca.vc, cb.vc));
            #pragma unroll
            for (int j = 1; j < SH; ++j) {
                u64 ma = mul2(ca.nB2, ca.vp);
                u64 mb = mul2(cb.nB2, cb.vp);
                u64 na = fma2(ca.A2, ca.vc, ma);
                u64 nb = fma2(cb.A2, cb.vc, mb);
                ca.vp = ca.vc; ca.vc = na;
                cb.vp = cb.vc; cb.vc = nb;
                acc[j] = add2(acc[j], add2(na, nb));
            }
        }

        // warp transpose-reduce: lane l ends owning sample pair (2l, 2l+1)
        #pragma unroll
        for (int stage = 0; stage < 5; ++stage) {
            const int d = 16 >> stage;
            const bool hi = (lane & d) != 0;
            #pragma unroll
            for (int j = 0; j < (16 >> stage); ++j) {
                const int mm = 16 >> stage;
                u64 a_ = acc[j], b_ = acc[j + mm];
                u64 send = hi ? a_ : b_;
                u64 keep = hi ? b_ : a_;
                u64 recv = __shfl_xor_sync(0xFFFFFFFFu, send, d);
                acc[j] = add2(keep, recv);
            }
        }

        sred[warp][lane] = acc[0];
        __syncthreads();

        if (threadIdx.x < SCHUNK) {
            const int j = threadIdx.x;
            const float* f = (const float*)sred;    // row stride = 66 floats
            float v = 0.0f;
            #pragma unroll
            for (int w = 0; w < 8; ++w) v += f[w * 66 + j];

            int sample = n0 + j;
            float av = fabsf(v);
            if (sample < N) out[sample] = v; else av = 0.0f;
            #pragma unroll
            for (int o = 16; o > 0; o >>= 1)
                av = fmaxf(av, __shfl_xor_sync(0xFFFFFFFFu, av, o));
            if (lane == 0) atomicMax(&gPeakBits, __float_as_uint(av));
        }
        __syncthreads();                            // sred reuse safety
    }

    grid_barrier(&gSyncB, &gFlagB);

    // ---- Phase C: normalize -------------------------------------------------
    float peak = __uint_as_float(gPeakBits) + 1e-8f;
    for (int idx = blockIdx.x * 256 + threadIdx.x; idx < N; idx += gridDim.x * 256)
        out[idx] = out[idx] / peak;
}

// ---------------------------------------------------------------------------
extern "C" void kernel_launch(void* const* d_in, const int* in_sizes, int n_in,
                              void* d_out, int out_size)
{
    const float* mu  = (const float*)d_in[0];
    const float* Dm  = (const float*)d_in[1];
    const float* T0m = (const float*)d_in[2];
    const float* Lyr = (const float*)d_in[3];
    const float* xr  = (const float*)d_in[4];
    const float* yr  = (const float*)d_in[5];
    int N  = out_size;                          // == num_samples
    int NC = (N + SCHUNK - 1) / SCHUNK;
    float* out = (float*)d_out;

    s1_kernel<<<GROUPS, GSZ>>>(mu, Dm, T0m, Lyr, xr, yr, NC);
    s2_kernel<<<1, 1024>>>(NC);
    plate_kernel<<<PBLK, 256>>>(out, N, NC);
}

// round 15
// speedup vs baseline: 1.3775x; 1.3775x over previous
#include <cuda_runtime.h>
#include <math.h>

#define NMODES 6400
#define MMAX 80
#define SCHUNK 64          // samples per chunk
#define SH 32              // SCHUNK/2 packed f32x2 accumulators
#define PBLK 296           // persistent blocks = 2/SM * 148 (co-resident)

typedef unsigned long long u64;

// ---------------- static device scratch (no runtime allocation) -------------
__device__ float4 gA[NMODES];        // {a2, -b2, C, r=e^{-sigK}}
__device__ float4 gB[NMODES];        // {thK, sth, cth, sigK (NaN if invalid)}
__device__ unsigned int gPeakBits;
// sense-reversing barriers: state self-restores after each use -> replay-safe
__device__ unsigned int gBC[2] = {0u, 0u};
__device__ volatile unsigned int gBS[2] = {0u, 0u};

// ---------------- f32x2 packed helpers (Blackwell FFMA2 path) ---------------
__device__ __forceinline__ u64 pack2(float lo, float hi) {
    u64 r; asm("mov.b64 %0, {%1, %2};" : "=l"(r) : "f"(lo), "f"(hi)); return r;
}
__device__ __forceinline__ u64 fma2(u64 a, u64 b, u64 c) {
    u64 d; asm("fma.rn.f32x2 %0, %1, %2, %3;" : "=l"(d) : "l"(a), "l"(b), "l"(c)); return d;
}
__device__ __forceinline__ u64 mul2(u64 a, u64 b) {
    u64 d; asm("mul.rn.f32x2 %0, %1, %2;" : "=l"(d) : "l"(a), "l"(b)); return d;
}
__device__ __forceinline__ u64 add2(u64 a, u64 b) {
    u64 d; asm("add.rn.f32x2 %0, %1, %2;" : "=l"(d) : "l"(a), "l"(b)); return d;
}

__device__ __forceinline__ float softplusf(float x) {
    return (x > 20.0f) ? x : log1pf(expf(x));
}

// sense-reversing grid barrier (all blocks co-resident; one use per id/launch)
__device__ __forceinline__ void grid_barrier(int id)
{
    __threadfence();
    __syncthreads();
    if (threadIdx.x == 0) {
        unsigned s = gBS[id];
        unsigned old = atomicAdd(&gBC[id], 1u);
        if (old == (unsigned)gridDim.x - 1u) {
            gBC[id] = 0u;                       // restore for next use/replay
            __threadfence();
            gBS[id] = s ^ 1u;                   // release
        } else {
            while (gBS[id] == s) {}
        }
    }
    __syncthreads();
    __threadfence();
}

// ---------------------------------------------------------------------------
// Fused persistent kernel: [setup] -> barrier -> [chunks] -> barrier -> [norm]
// ---------------------------------------------------------------------------
struct Chain { u64 vc, vp, A2, nB2; };

__device__ __forceinline__ Chain seed_chain(float4 A, float4 B,
                                            float n0f, float n0m1, bool on)
{
    float s0, c0;
    sincosf(n0f * B.x, &s0, &c0);               // accurate phase re-seed
    float E0   = __expf(-B.w * n0m1);           // NaN for invalid -> on=false
    float r    = A.w;                           // e^{-sigK} precomputed
    float rinv = __frcp_rn(r);

    float sp1 = fmaf(s0, B.z,  c0 * B.y);       // sin((n0+1)θ)
    float sm1 = fmaf(s0, B.z, -c0 * B.y);       // sin((n0-1)θ)
    float sm2 = fmaf(2.0f * B.z, sm1, -s0);     // sin((n0-2)θ)

    float CE = on ? (A.z * E0) : 0.0f;          // SEL: NaN-safe when off
    Chain ch;
    ch.vc  = pack2(CE * s0, CE * r * sp1);                     // y(n0), y(n0+1)
    ch.vp  = pack2(CE * (rinv * rinv) * sm2, CE * rinv * sm1); // y(n0-2), y(n0-1)
    ch.A2  = pack2(A.x, A.x);
    ch.nB2 = pack2(A.y, A.y);
    return ch;
}

__global__ void __launch_bounds__(256, 2) plate_kernel(
    float* __restrict__ out, int N, int NC,
    const float* __restrict__ pmu, const float* __restrict__ pD,
    const float* __restrict__ pT0, const float* __restrict__ pLy,
    const float* __restrict__ pxo, const float* __restrict__ pyo)
{
    const int lane = threadIdx.x & 31;
    const int warp = threadIdx.x >> 5;
    __shared__ u64 sred[8][33];

    // ---- Phase 0: per-mode setup (threads 0..NMODES-1, one mode each) ------
    {
        const int i = blockIdx.x * 256 + threadIdx.x;
        if (i == 0) gPeakBits = 0u;
        if (i < NMODES) {
            float mu   = softplusf(pmu[0]) + 1e-4f;
            float Dmu  = softplusf(pD[0])  + 1e-4f;
            float T0mu = softplusf(pT0[0]) + 1e-4f;
            float Ly = 1.1f + (4.0f - 1.1f) * ((tanhf(pLy[0]) + 1.0f) * 0.5f);
            const float LX = 0.5f;
            float xo = 0.49f * LX + (1.0f - 0.49f) * LX * ((tanhf(pxo[0]) + 1.0f) * 0.5f);
            float yo = 0.51f * Ly + (1.0f - 0.51f) * Ly * ((tanhf(pyo[0]) + 1.0f) * 0.5f);

            const float PI  = 3.14159265358979323846f;
            const float Kf  = (float)(1.0 / 44100.0);
            const float MAXOM = (float)(10000.0 * 2.0 * 3.141592653589793);
            const float MINOM = (float)(20.0 * 2.0 * 3.141592653589793);
            const double OM2   = 2.0 * 3.141592653589793 * 500.0;
            const double DOMSQ = OM2 * OM2;
            const double LN10T3 = 3.0 * 2.302585092994045684;
            const float ALPHA = (float)(LN10T3 / DOMSQ * (DOMSQ / 6.0));
            const float BETA  = (float)(LN10T3 / DOMSQ * (1.0 / 1.0 - 1.0 / 6.0));

            float m  = (float)(i / MMAX + 1);
            float nn = (float)(i % MMAX + 1);

            // omega / validity path identical (fp32) to known-passing kernels
            float t1 = (m * PI) / LX;
            float t2 = (nn * PI) / Ly;
            float g1 = t1 * t1 + t2 * t2;
            float w2 = T0mu * g1 + (Dmu * g1) * g1;
            w2 = fmaxf(w2, 0.0f);
            float omega = sqrtf(w2);
            int valid = (omega <= MAXOM) && (omega >= MINOM);

            float sigma = ALPHA + BETA * (omega * omega);
            float xi = 0.1f * LX, yi = 0.1f * Ly;
            float in_w  = cosf(((xi * PI) * m) / LX) * cosf(((yi * PI) * nn) / Ly);
            float out_w = cosf(((xo * PI) * m) / LX) * cosf(((yo * PI) * nn) / Ly);
            float ms = 0.25f * mu * LX * Ly;
            float P  = out_w * in_w * (Kf * Kf) * expf(-sigma * Kf) / ms;

            float thK  = omega * Kf;
            float sigK = sigma * Kf;

            float sth, cth;
            sincosf(thK, &sth, &cth);
            float r   = expf(-sigK);
            float r2  = r * r;
            float c2  = fmaf(-2.0f * sth, sth, 1.0f);  // cos(2θ) = 1 - 2 sin²
            float a2  = 2.0f * r2 * c2;
            float nb2 = -(r2 * r2);
            float C   = P / (sth + 1e-8f);

            // invalid: sigK := NaN so (n0m1 * sigK <= 20) is ALWAYS false
            float sigKst = valid ? sigK : __int_as_float(0x7FC00000);

            gA[i] = make_float4(a2, nb2, C, r);
            gB[i] = make_float4(thK, sth, cth, sigKst);
        }
    }
    grid_barrier(0);

    // ---- Phase B: chunks, static stride; warp-coherent 64-mode windows -----
    const int wbase = warp * 64 + lane;          // lane slot in 512-mode stride
    for (int c = blockIdx.x; c < NC; c += gridDim.x) {
        const int n0 = c * SCHUNK;
        const float n0f  = (float)n0;
        const float n0m1 = n0f - 1.0f;

        u64 acc[SH];
        #pragma unroll
        for (int j = 0; j < SH; ++j) acc[j] = 0ull;

        #pragma unroll 1
        for (int base = 0; base < NMODES; base += 512) {
            int i1 = base + wbase;               // warp window [*, *+64)
            if (i1 >= NMODES) continue;          // uniform within warp
            int i2 = i1 + 32;                    // windows 64-aligned: valid

            float4 B1 = gB[i1];
            float4 B2 = gB[i2];
            bool on1 = (n0m1 * B1.w <= 20.0f);   // NaN-coded invalid -> false
            bool on2 = (n0m1 * B2.w <= 20.0f);
            if (!on1 && !on2) continue;          // coherent: 64 adjacent modes

            float4 A1 = gA[i1];
            float4 A2_ = gA[i2];
            Chain ca = seed_chain(A1, B1, n0f, n0m1, on1);
            Chain cb = seed_chain(A2_, B2, n0f, n0m1, on2);

            acc[0] = add2(acc[0], add2(ca.vc, cb.vc));
            #pragma unroll
            for (int j = 1; j < SH; ++j) {
                u64 ma = mul2(ca.nB2, ca.vp);
                u64 mb = mul2(cb.nB2, cb.vp);
                u64 na = fma2(ca.A2, ca.vc, ma);
                u64 nb = fma2(cb.A2, cb.vc, mb);
                ca.vp = ca.vc; ca.vc = na;
                cb.vp = cb.vc; cb.vc = nb;
                acc[j] = add2(acc[j], add2(na, nb));
            }
        }

        // warp transpose-reduce: lane l ends owning sample pair (2l, 2l+1)
        #pragma unroll
        for (int stage = 0; stage < 5; ++stage) {
            const int d = 16 >> stage;
            const bool hi = (lane & d) != 0;
            #pragma unroll
            for (int j = 0; j < (16 >> stage); ++j) {
                const int mm = 16 >> stage;
                u64 a_ = acc[j], b_ = acc[j + mm];
                u64 send = hi ? a_ : b_;
                u64 keep = hi ? b_ : a_;
                u64 recv = __shfl_xor_sync(0xFFFFFFFFu, send, d);
                acc[j] = add2(keep, recv);
            }
        }

        sred[warp][lane] = acc[0];
        __syncthreads();

        if (threadIdx.x < SCHUNK) {
            const int j = threadIdx.x;
            const float* f = (const float*)sred;    // row stride = 66 floats
            float v = 0.0f;
            #pragma unroll
            for (int w = 0; w < 8; ++w) v += f[w * 66 + j];

            int sample = n0 + j;
            float av = fabsf(v);
            if (sample < N) out[sample] = v; else av = 0.0f;
            #pragma unroll
            for (int o = 16; o > 0; o >>= 1)
                av = fmaxf(av, __shfl_xor_sync(0xFFFFFFFFu, av, o));
            if (lane == 0) atomicMax(&gPeakBits, __float_as_uint(av));
        }
        __syncthreads();                            // sred reuse safety
    }

    grid_barrier(1);

    // ---- Phase C: normalize ------------------------------------------------
    float peak = __uint_as_float(gPeakBits) + 1e-8f;
    for (int idx = blockIdx.x * 256 + threadIdx.x; idx < N; idx += gridDim.x * 256)
        out[idx] = out[idx] / peak;
}

// ---------------------------------------------------------------------------
extern "C" void kernel_launch(void* const* d_in, const int* in_sizes, int n_in,
                              void* d_out, int out_size)
{
    const float* mu  = (const float*)d_in[0];
    const float* Dm  = (const float*)d_in[1];
    const float* T0m = (const float*)d_in[2];
    const float* Lyr = (const float*)d_in[3];
    const float* xr  = (const float*)d_in[4];
    const float* yr  = (const float*)d_in[5];
    int N  = out_size;                          // == num_samples
    int NC = (N + SCHUNK - 1) / SCHUNK;
    float* out = (float*)d_out;

    plate_kernel<<<PBLK, 256>>>(out, N, NC, mu, Dm, T0m, Lyr, xr, yr);
}